// round 3
// baseline (speedup 1.0000x reference)
#include <cuda_runtime.h>

#define T_LEN 4096
#define B_SZ  512
#define NIN   42
#define NH    9
#define G4    36             // 4*NH
#define ROWS  (T_LEN * B_SZ) // 2097152
#define KP    44             // padded K (multiple of 4)
#define RT    128            // rows per producer block (4 blocks per t)
#define STRIDE (B_SZ * NH)   // 4608
#define NCONS 57             // consumer blocks (9 warps x 1 elem)
#define NPROD (ROWS / RT)    // 16384
#define CH_T  16             // timesteps per sync chunk
#define NCHUNK (T_LEN / CH_T)   // 256
#define BLK_PER_CH 64        // producer blocks per chunk (4 * CH_T)

// Scratch: gates (i,f,g,o) per (row, j), biases folded in (~302 MB) + counters.
__device__ float4 g_xpre[(size_t)ROWS * NH];
__device__ int    g_done[NCHUNK];

__global__ void clear_kernel() {
    int i = blockIdx.x * blockDim.x + threadIdx.x;
    if (i < NCHUNK) g_done[i] = 0;
}

// ---------------------------------------------------------------------------
// helpers
// ---------------------------------------------------------------------------
__device__ __forceinline__ int ld_acq(const int* p) {
    int v;
    asm volatile("ld.global.acquire.gpu.b32 %0, [%1];" : "=r"(v) : "l"(p));
    return v;
}
__device__ __forceinline__ float tanh_ap(float x) {
    float y;
    asm("tanh.approx.f32 %0, %1;" : "=f"(y) : "f"(x));
    return y;
}
__device__ __forceinline__ float sig_ap(float x) {
    return fmaf(0.5f, tanh_ap(0.5f * x), 0.5f);
}
__device__ __forceinline__ float4 ldcg4(const float4* p) {
    float4 v;
    asm volatile("ld.global.cg.v4.f32 {%0,%1,%2,%3}, [%4];"
                 : "=f"(v.x), "=f"(v.y), "=f"(v.z), "=f"(v.w) : "l"(p));
    return v;
}
__device__ __forceinline__ void wait_chunk(int n) {
    if (ld_acq(&g_done[n]) >= BLK_PER_CH) return;
    while (ld_acq(&g_done[n]) < BLK_PER_CH) __nanosleep(60);
}

// ---------------------------------------------------------------------------
// One LSTM step (lane j of a single batch element per warp; shfl base = 0)
// ---------------------------------------------------------------------------
#define LSTM_STEP(XP, TT) do {                                                \
    float a0 = (XP).x, a1 = (XP).y, a2 = (XP).z, a3 = (XP).w;                 \
    float d0 = 0.f, d1 = 0.f, d2 = 0.f, d3 = 0.f;                             \
    _Pragma("unroll")                                                         \
    for (int k = 0; k < 9; k++) {                                             \
        float hk = __shfl_sync(0xFFFFFFFFu, h, k);                            \
        if (k < 5) {                                                          \
            a0 = fmaf(Wi[k], hk, a0); a1 = fmaf(Wf[k], hk, a1);               \
            a2 = fmaf(Wg[k], hk, a2); a3 = fmaf(Wo[k], hk, a3);               \
        } else {                                                              \
            d0 = fmaf(Wi[k], hk, d0); d1 = fmaf(Wf[k], hk, d1);               \
            d2 = fmaf(Wg[k], hk, d2); d3 = fmaf(Wo[k], hk, d3);               \
        }                                                                     \
    }                                                                         \
    float ig = sig_ap(a0 + d0);                                               \
    float fg = sig_ap(a1 + d1);                                               \
    float gg = tanh_ap(a2 + d2);                                              \
    float og = sig_ap(a3 + d3);                                               \
    c = fmaf(fg, c, ig * gg);                                                 \
    h = og * tanh_ap(c);                                                      \
    if (valid) out[(TT) * STRIDE + base_idx] = h;                             \
} while (0)

// ---------------------------------------------------------------------------
// Fused kernel. Blocks [0, NCONS): consumers (9 warps, 1 batch elem each).
// Blocks [NCONS, NCONS+NPROD): producers (input projection, 1 block = 128 rows).
// ---------------------------------------------------------------------------
__global__ __launch_bounds__(288, 3) void fused_kernel(
    const float* __restrict__ x,    const float* __restrict__ h_in,
    const float* __restrict__ c_in, const float* __restrict__ Wih,
    const float* __restrict__ Whh,  const float* __restrict__ bih,
    const float* __restrict__ bhh,  float* __restrict__ out)
{
    __shared__ float xs[RT * KP];
    __shared__ float ws[G4 * KP];

    if (blockIdx.x < NCONS) {
        // ================= CONSUMER =================
        const int lane = threadIdx.x & 31;
        const int w    = threadIdx.x >> 5;        // warp -> element
        const int b0   = blockIdx.x * 9 + w;
        const int j    = (lane < 9) ? lane : 8;
        const bool valid = (lane < 9) && (b0 < B_SZ);
        const int b    = (b0 < B_SZ) ? b0 : (B_SZ - 1);

        float Wi[NH], Wf[NH], Wg[NH], Wo[NH];
        #pragma unroll
        for (int k = 0; k < NH; k++) {
            Wi[k] = Whh[(0 * NH + j) * NH + k];
            Wf[k] = Whh[(1 * NH + j) * NH + k];
            Wg[k] = Whh[(2 * NH + j) * NH + k];
            Wo[k] = Whh[(3 * NH + j) * NH + k];
        }
        float h = h_in[b * NH + j];
        float c = c_in[b * NH + j];

        const int base_idx = b * NH + j;
        const float4* xp = g_xpre;

        wait_chunk(0);
        float4 f0 = ldcg4(xp + 0 * STRIDE + base_idx);
        float4 f1 = ldcg4(xp + 1 * STRIDE + base_idx);
        float4 f2 = ldcg4(xp + 2 * STRIDE + base_idx);
        float4 f3 = ldcg4(xp + 3 * STRIDE + base_idx);

        int t = 0;
        for (; t < T_LEN - 4; t += 4) {
            // Entering a new chunk's data with the prefetch group? Sync once.
            if (((t + 4) & (CH_T - 1)) == 0) wait_chunk((t + 4) >> 4);
            float4 n0 = ldcg4(xp + (t + 4) * STRIDE + base_idx);
            float4 n1 = ldcg4(xp + (t + 5) * STRIDE + base_idx);
            float4 n2 = ldcg4(xp + (t + 6) * STRIDE + base_idx);
            float4 n3 = ldcg4(xp + (t + 7) * STRIDE + base_idx);
            LSTM_STEP(f0, t + 0);
            LSTM_STEP(f1, t + 1);
            LSTM_STEP(f2, t + 2);
            LSTM_STEP(f3, t + 3);
            f0 = n0; f1 = n1; f2 = n2; f3 = n3;
        }
        LSTM_STEP(f0, t + 0);
        LSTM_STEP(f1, t + 1);
        LSTM_STEP(f2, t + 2);
        LSTM_STEP(f3, t + 3);

        if (valid) {
            out[(size_t)T_LEN * STRIDE + base_idx]          = h;  // hn
            out[(size_t)T_LEN * STRIDE + STRIDE + base_idx] = c;  // cn
        }
        return;
    }

    // ================= PRODUCER =================
    const int tid  = threadIdx.x;
    const int p    = blockIdx.x - NCONS;
    const int row0 = p * RT;

    // Stage W_ih, reindexed: ws[(j*4+g)*KP + k] = W_ih[(g*9+j)*42 + k]
    for (int i = tid; i < G4 * NIN; i += 288) {
        int r = i / NIN, k = i - r * NIN;
        int g = r / NH,  j = r - g * NH;
        ws[(j * 4 + g) * KP + k] = Wih[i];
    }
    for (int i = tid; i < G4 * (KP - NIN); i += 288) {
        int r = i / (KP - NIN);
        ws[r * KP + NIN + (i - r * (KP - NIN))] = 0.f;
    }
    // Stage x tile (contiguous global span), zero-pad cols 42..43.
    const float* xg = x + (size_t)row0 * NIN;
    for (int i = tid; i < RT * NIN; i += 288) {
        int r = i / NIN;
        xs[r * KP + (i - r * NIN)] = xg[i];
    }
    for (int i = tid; i < RT * (KP - NIN); i += 288) {
        int r = i >> 1;
        xs[r * KP + NIN + (i & 1)] = 0.f;
    }
    __syncthreads();

    const int j    = tid >> 5;   // warp = hidden unit j
    const int lane = tid & 31;

    float acc[4][4];
    #pragma unroll
    for (int r = 0; r < 4; r++)
        #pragma unroll
        for (int g = 0; g < 4; g++) acc[r][g] = 0.f;

    const float4* wv = (const float4*)ws + j * 4 * (KP / 4);
    const float4* xv = (const float4*)xs;

    #pragma unroll
    for (int cch = 0; cch < KP / 4; cch++) {
        float4 w0 = wv[0 * (KP / 4) + cch];
        float4 w1 = wv[1 * (KP / 4) + cch];
        float4 w2 = wv[2 * (KP / 4) + cch];
        float4 w3 = wv[3 * (KP / 4) + cch];
        #pragma unroll
        for (int r = 0; r < 4; r++) {
            float4 xr = xv[(lane + 32 * r) * (KP / 4) + cch];
            acc[r][0] = fmaf(w0.x, xr.x, acc[r][0]);
            acc[r][0] = fmaf(w0.y, xr.y, acc[r][0]);
            acc[r][0] = fmaf(w0.z, xr.z, acc[r][0]);
            acc[r][0] = fmaf(w0.w, xr.w, acc[r][0]);
            acc[r][1] = fmaf(w1.x, xr.x, acc[r][1]);
            acc[r][1] = fmaf(w1.y, xr.y, acc[r][1]);
            acc[r][1] = fmaf(w1.z, xr.z, acc[r][1]);
            acc[r][1] = fmaf(w1.w, xr.w, acc[r][1]);
            acc[r][2] = fmaf(w2.x, xr.x, acc[r][2]);
            acc[r][2] = fmaf(w2.y, xr.y, acc[r][2]);
            acc[r][2] = fmaf(w2.z, xr.z, acc[r][2]);
            acc[r][2] = fmaf(w2.w, xr.w, acc[r][2]);
            acc[r][3] = fmaf(w3.x, xr.x, acc[r][3]);
            acc[r][3] = fmaf(w3.y, xr.y, acc[r][3]);
            acc[r][3] = fmaf(w3.z, xr.z, acc[r][3]);
            acc[r][3] = fmaf(w3.w, xr.w, acc[r][3]);
        }
    }

    float bsum[4];
    #pragma unroll
    for (int g = 0; g < 4; g++) bsum[g] = bih[g * NH + j] + bhh[g * NH + j];

    #pragma unroll
    for (int r = 0; r < 4; r++) {
        int row = row0 + lane + 32 * r;
        float4 o;
        o.x = acc[r][0] + bsum[0];
        o.y = acc[r][1] + bsum[1];
        o.z = acc[r][2] + bsum[2];
        o.w = acc[r][3] + bsum[3];
        g_xpre[(size_t)row * NH + j] = o;
    }

    // Signal chunk completion (64 producer blocks per 16-timestep chunk).
    __threadfence();
    __syncthreads();
    if (tid == 0) atomicAdd(&g_done[p >> 6], 1);
}

// ---------------------------------------------------------------------------
extern "C" void kernel_launch(void* const* d_in, const int* in_sizes, int n_in,
                              void* d_out, int out_size) {
    const float* x   = (const float*)d_in[0];
    const float* h   = (const float*)d_in[1];
    const float* c   = (const float*)d_in[2];
    const float* Wih = (const float*)d_in[3];
    const float* Whh = (const float*)d_in[4];
    const float* bih = (const float*)d_in[5];
    const float* bhh = (const float*)d_in[6];
    float* out = (float*)d_out;

    clear_kernel<<<1, 256>>>();
    fused_kernel<<<NCONS + NPROD, 288>>>(x, h, c, Wih, Whh, bih, bhh, out);
}

// round 4
// speedup vs baseline: 1.6942x; 1.6942x over previous
#include <cuda_runtime.h>

#define T_LEN 4096
#define B_SZ  512
#define NIN   42
#define NH    9
#define G4    36             // 4*NH
#define ROWS  (T_LEN * B_SZ) // 2097152
#define KP    44             // padded K (multiple of 4)
#define RT    128            // rows per producer block
#define STRIDE (B_SZ * NH)   // 4608
#define NCONS 57             // consumer blocks (9 warps x 1 elem each)

// Scratch: gates (i,f,g,o) per (row, j), biases folded in (~302 MB).
__device__ float4 g_xpre[(size_t)ROWS * NH];

// ---------------------------------------------------------------------------
// Kernel 1 (producer): x_pre[row][j] = {i,f,g,o} pre-activations, biases folded.
// ---------------------------------------------------------------------------
__global__ __launch_bounds__(288, 4) void xproj_kernel(
    const float* __restrict__ x, const float* __restrict__ Wih,
    const float* __restrict__ bih, const float* __restrict__ bhh)
{
    __shared__ float xs[RT * KP];
    __shared__ float ws[G4 * KP];
    const int tid  = threadIdx.x;
    const int row0 = blockIdx.x * RT;

    // Stage W_ih, reindexed: ws[(j*4+g)*KP + k] = W_ih[(g*9+j)*42 + k]
    for (int i = tid; i < G4 * NIN; i += 288) {
        int r = i / NIN, k = i - r * NIN;
        int g = r / NH,  j = r - g * NH;
        ws[(j * 4 + g) * KP + k] = Wih[i];
    }
    for (int i = tid; i < G4 * (KP - NIN); i += 288) {
        int r = i / (KP - NIN);
        ws[r * KP + NIN + (i - r * (KP - NIN))] = 0.f;
    }
    // Stage x tile (contiguous global span), zero-pad cols 42..43.
    const float* xg = x + (size_t)row0 * NIN;
    for (int i = tid; i < RT * NIN; i += 288) {
        int r = i / NIN;
        xs[r * KP + (i - r * NIN)] = xg[i];
    }
    for (int i = tid; i < RT * (KP - NIN); i += 288) {
        int r = i >> 1;
        xs[r * KP + NIN + (i & 1)] = 0.f;
    }
    __syncthreads();

    const int j    = tid >> 5;   // warp = hidden unit j (0..8)
    const int lane = tid & 31;

    float acc[4][4];
    #pragma unroll
    for (int r = 0; r < 4; r++)
        #pragma unroll
        for (int g = 0; g < 4; g++) acc[r][g] = 0.f;

    const float4* wv = (const float4*)ws + j * 4 * (KP / 4);
    const float4* xv = (const float4*)xs;

    #pragma unroll
    for (int cch = 0; cch < KP / 4; cch++) {
        float4 w0 = wv[0 * (KP / 4) + cch];
        float4 w1 = wv[1 * (KP / 4) + cch];
        float4 w2 = wv[2 * (KP / 4) + cch];
        float4 w3 = wv[3 * (KP / 4) + cch];
        #pragma unroll
        for (int r = 0; r < 4; r++) {
            float4 xr = xv[(lane + 32 * r) * (KP / 4) + cch];
            acc[r][0] = fmaf(w0.x, xr.x, acc[r][0]);
            acc[r][0] = fmaf(w0.y, xr.y, acc[r][0]);
            acc[r][0] = fmaf(w0.z, xr.z, acc[r][0]);
            acc[r][0] = fmaf(w0.w, xr.w, acc[r][0]);
            acc[r][1] = fmaf(w1.x, xr.x, acc[r][1]);
            acc[r][1] = fmaf(w1.y, xr.y, acc[r][1]);
            acc[r][1] = fmaf(w1.z, xr.z, acc[r][1]);
            acc[r][1] = fmaf(w1.w, xr.w, acc[r][1]);
            acc[r][2] = fmaf(w2.x, xr.x, acc[r][2]);
            acc[r][2] = fmaf(w2.y, xr.y, acc[r][2]);
            acc[r][2] = fmaf(w2.z, xr.z, acc[r][2]);
            acc[r][2] = fmaf(w2.w, xr.w, acc[r][2]);
            acc[r][3] = fmaf(w3.x, xr.x, acc[r][3]);
            acc[r][3] = fmaf(w3.y, xr.y, acc[r][3]);
            acc[r][3] = fmaf(w3.z, xr.z, acc[r][3]);
            acc[r][3] = fmaf(w3.w, xr.w, acc[r][3]);
        }
    }

    float bsum[4];
    #pragma unroll
    for (int g = 0; g < 4; g++) bsum[g] = bih[g * NH + j] + bhh[g * NH + j];

    #pragma unroll
    for (int r = 0; r < 4; r++) {
        int row = row0 + lane + 32 * r;
        float4 o;
        o.x = acc[r][0] + bsum[0];
        o.y = acc[r][1] + bsum[1];
        o.z = acc[r][2] + bsum[2];
        o.w = acc[r][3] + bsum[3];
        g_xpre[(size_t)row * NH + j] = o;
    }
}

// ---------------------------------------------------------------------------
// Kernel 2 (consumer): 9 warps/block, each warp = ONE batch element.
// Lane j (0..8) owns hidden unit j; W_hh in registers; h exchanged via shfl.
// tanh.approx activations; 8-step-deep x_pre prefetch.
// ---------------------------------------------------------------------------
__device__ __forceinline__ float tanh_ap(float x) {
    float y;
    asm("tanh.approx.f32 %0, %1;" : "=f"(y) : "f"(x));
    return y;
}
__device__ __forceinline__ float sig_ap(float x) {
    return fmaf(0.5f, tanh_ap(0.5f * x), 0.5f);
}

#define LSTM_STEP(XP, TT) do {                                                \
    float a0 = (XP).x, a1 = (XP).y, a2 = (XP).z, a3 = (XP).w;                 \
    float d0 = 0.f, d1 = 0.f, d2 = 0.f, d3 = 0.f;                             \
    _Pragma("unroll")                                                         \
    for (int k = 0; k < 9; k++) {                                             \
        float hk = __shfl_sync(0xFFFFFFFFu, h, k);                            \
        if (k < 5) {                                                          \
            a0 = fmaf(Wi[k], hk, a0); a1 = fmaf(Wf[k], hk, a1);               \
            a2 = fmaf(Wg[k], hk, a2); a3 = fmaf(Wo[k], hk, a3);               \
        } else {                                                              \
            d0 = fmaf(Wi[k], hk, d0); d1 = fmaf(Wf[k], hk, d1);               \
            d2 = fmaf(Wg[k], hk, d2); d3 = fmaf(Wo[k], hk, d3);               \
        }                                                                     \
    }                                                                         \
    float ig = sig_ap(a0 + d0);                                               \
    float fg = sig_ap(a1 + d1);                                               \
    float gg = tanh_ap(a2 + d2);                                              \
    float og = sig_ap(a3 + d3);                                               \
    c = fmaf(fg, c, ig * gg);                                                 \
    h = og * tanh_ap(c);                                                      \
    if (valid) out[(TT) * STRIDE + base_idx] = h;                             \
} while (0)

__global__ __launch_bounds__(288) void lstm_rec_kernel(
    const float* __restrict__ h_in, const float* __restrict__ c_in,
    const float* __restrict__ Whh, float* __restrict__ out)
{
    const int lane = threadIdx.x & 31;
    const int w    = threadIdx.x >> 5;        // warp index -> batch element
    const int b0   = blockIdx.x * 9 + w;
    const int j    = (lane < 9) ? lane : 8;
    const bool valid = (lane < 9) && (b0 < B_SZ);
    const int b    = (b0 < B_SZ) ? b0 : (B_SZ - 1);

    float Wi[NH], Wf[NH], Wg[NH], Wo[NH];
    #pragma unroll
    for (int k = 0; k < NH; k++) {
        Wi[k] = Whh[(0 * NH + j) * NH + k];
        Wf[k] = Whh[(1 * NH + j) * NH + k];
        Wg[k] = Whh[(2 * NH + j) * NH + k];
        Wo[k] = Whh[(3 * NH + j) * NH + k];
    }
    float h = h_in[b * NH + j];
    float c = c_in[b * NH + j];

    const int base_idx = b * NH + j;
    const float4* xp = g_xpre;

    // 8-step-deep prefetch pipeline (two float4 groups in flight).
    float4 f0 = xp[0 * STRIDE + base_idx];
    float4 f1 = xp[1 * STRIDE + base_idx];
    float4 f2 = xp[2 * STRIDE + base_idx];
    float4 f3 = xp[3 * STRIDE + base_idx];
    float4 n0 = xp[4 * STRIDE + base_idx];
    float4 n1 = xp[5 * STRIDE + base_idx];
    float4 n2 = xp[6 * STRIDE + base_idx];
    float4 n3 = xp[7 * STRIDE + base_idx];

    int t = 0;
    for (; t < T_LEN - 8; t += 4) {
        float4 m0 = xp[(t +  8) * STRIDE + base_idx];
        float4 m1 = xp[(t +  9) * STRIDE + base_idx];
        float4 m2 = xp[(t + 10) * STRIDE + base_idx];
        float4 m3 = xp[(t + 11) * STRIDE + base_idx];
        LSTM_STEP(f0, t + 0);
        LSTM_STEP(f1, t + 1);
        LSTM_STEP(f2, t + 2);
        LSTM_STEP(f3, t + 3);
        f0 = n0; f1 = n1; f2 = n2; f3 = n3;
        n0 = m0; n1 = m1; n2 = m2; n3 = m3;
    }
    // t = 4088: f covers 4088..4091, n covers 4092..4095
    LSTM_STEP(f0, t + 0);
    LSTM_STEP(f1, t + 1);
    LSTM_STEP(f2, t + 2);
    LSTM_STEP(f3, t + 3);
    LSTM_STEP(n0, t + 4);
    LSTM_STEP(n1, t + 5);
    LSTM_STEP(n2, t + 6);
    LSTM_STEP(n3, t + 7);

    if (valid) {
        out[(size_t)T_LEN * STRIDE + base_idx]          = h;  // hn
        out[(size_t)T_LEN * STRIDE + STRIDE + base_idx] = c;  // cn
    }
}

// ---------------------------------------------------------------------------
extern "C" void kernel_launch(void* const* d_in, const int* in_sizes, int n_in,
                              void* d_out, int out_size) {
    const float* x   = (const float*)d_in[0];
    const float* h   = (const float*)d_in[1];
    const float* c   = (const float*)d_in[2];
    const float* Wih = (const float*)d_in[3];
    const float* Whh = (const float*)d_in[4];
    const float* bih = (const float*)d_in[5];
    const float* bhh = (const float*)d_in[6];
    float* out = (float*)d_out;

    xproj_kernel<<<ROWS / RT, 288>>>(x, Wih, bih, bhh);
    lstm_rec_kernel<<<NCONS, 288>>>(h, c, Whh, out);
}

// round 5
// speedup vs baseline: 1.9644x; 1.1595x over previous
#include <cuda_runtime.h>

#define T_LEN 4096
#define B_SZ  512
#define NIN   42
#define NH    9
#define G4    36             // 4*NH
#define ROWS  (T_LEN * B_SZ) // 2097152
#define KP    44             // padded K (multiple of 4)
#define RT    128            // rows per producer block
#define STRIDE (B_SZ * NH)   // 4608 floats per timestep (output)
#define SF4   4608           // float4s per timestep in g_xpre
#define NCONS 57             // consumer blocks (9 elems each)
#define CH    16             // timesteps per chunk
#define NCH   (T_LEN / CH)   // 256
#define UPB   81             // float4s per (t, block) slab: 9 elems x 9 units

// Scratch: gates (i,f,g,o) per (row, j), biases folded in (~302 MB).
__device__ float4 g_xpre[(size_t)ROWS * NH];

// ---------------------------------------------------------------------------
// Kernel 1 (producer): unchanged from R4 (measured 445us).
// ---------------------------------------------------------------------------
__global__ __launch_bounds__(288, 4) void xproj_kernel(
    const float* __restrict__ x, const float* __restrict__ Wih,
    const float* __restrict__ bih, const float* __restrict__ bhh)
{
    __shared__ float xs[RT * KP];
    __shared__ float ws[G4 * KP];
    const int tid  = threadIdx.x;
    const int row0 = blockIdx.x * RT;

    for (int i = tid; i < G4 * NIN; i += 288) {
        int r = i / NIN, k = i - r * NIN;
        int g = r / NH,  j = r - g * NH;
        ws[(j * 4 + g) * KP + k] = Wih[i];
    }
    for (int i = tid; i < G4 * (KP - NIN); i += 288) {
        int r = i / (KP - NIN);
        ws[r * KP + NIN + (i - r * (KP - NIN))] = 0.f;
    }
    const float* xg = x + (size_t)row0 * NIN;
    for (int i = tid; i < RT * NIN; i += 288) {
        int r = i / NIN;
        xs[r * KP + (i - r * NIN)] = xg[i];
    }
    for (int i = tid; i < RT * (KP - NIN); i += 288) {
        int r = i >> 1;
        xs[r * KP + NIN + (i & 1)] = 0.f;
    }
    __syncthreads();

    const int j    = tid >> 5;
    const int lane = tid & 31;

    float acc[4][4];
    #pragma unroll
    for (int r = 0; r < 4; r++)
        #pragma unroll
        for (int g = 0; g < 4; g++) acc[r][g] = 0.f;

    const float4* wv = (const float4*)ws + j * 4 * (KP / 4);
    const float4* xv = (const float4*)xs;

    #pragma unroll
    for (int cch = 0; cch < KP / 4; cch++) {
        float4 w0 = wv[0 * (KP / 4) + cch];
        float4 w1 = wv[1 * (KP / 4) + cch];
        float4 w2 = wv[2 * (KP / 4) + cch];
        float4 w3 = wv[3 * (KP / 4) + cch];
        #pragma unroll
        for (int r = 0; r < 4; r++) {
            float4 xr = xv[(lane + 32 * r) * (KP / 4) + cch];
            acc[r][0] = fmaf(w0.x, xr.x, acc[r][0]);
            acc[r][0] = fmaf(w0.y, xr.y, acc[r][0]);
            acc[r][0] = fmaf(w0.z, xr.z, acc[r][0]);
            acc[r][0] = fmaf(w0.w, xr.w, acc[r][0]);
            acc[r][1] = fmaf(w1.x, xr.x, acc[r][1]);
            acc[r][1] = fmaf(w1.y, xr.y, acc[r][1]);
            acc[r][1] = fmaf(w1.z, xr.z, acc[r][1]);
            acc[r][1] = fmaf(w1.w, xr.w, acc[r][1]);
            acc[r][2] = fmaf(w2.x, xr.x, acc[r][2]);
            acc[r][2] = fmaf(w2.y, xr.y, acc[r][2]);
            acc[r][2] = fmaf(w2.z, xr.z, acc[r][2]);
            acc[r][2] = fmaf(w2.w, xr.w, acc[r][2]);
            acc[r][3] = fmaf(w3.x, xr.x, acc[r][3]);
            acc[r][3] = fmaf(w3.y, xr.y, acc[r][3]);
            acc[r][3] = fmaf(w3.z, xr.z, acc[r][3]);
            acc[r][3] = fmaf(w3.w, xr.w, acc[r][3]);
        }
    }

    float bsum[4];
    #pragma unroll
    for (int g = 0; g < 4; g++) bsum[g] = bih[g * NH + j] + bhh[g * NH + j];

    #pragma unroll
    for (int r = 0; r < 4; r++) {
        int row = row0 + lane + 32 * r;
        float4 o;
        o.x = acc[r][0] + bsum[0];
        o.y = acc[r][1] + bsum[1];
        o.z = acc[r][2] + bsum[2];
        o.w = acc[r][3] + bsum[3];
        g_xpre[(size_t)row * NH + j] = o;
    }
}

// ---------------------------------------------------------------------------
// Consumer: 13 warps/block. Warps 0-8: compute (1 batch elem each, lane j owns
// hidden unit j, W_hh in regs, h via shfl). Warps 9-12: loaders streaming
// x_pre in 16-step chunks into a 2-deep smem ring.
// ---------------------------------------------------------------------------
__device__ __forceinline__ float tanh_ap(float x) {
    float y;
    asm("tanh.approx.f32 %0, %1;" : "=f"(y) : "f"(x));
    return y;
}
__device__ __forceinline__ float sig_ap(float x) {
    return fmaf(0.5f, tanh_ap(0.5f * x), 0.5f);
}
__device__ __forceinline__ float4 ldcg4(const float4* p) {
    float4 v;
    asm volatile("ld.global.cg.v4.f32 {%0,%1,%2,%3}, [%4];"
                 : "=f"(v.x), "=f"(v.y), "=f"(v.z), "=f"(v.w) : "l"(p));
    return v;
}
__device__ __forceinline__ int ld_acq_sh(const int* p) {
    unsigned a = (unsigned)__cvta_generic_to_shared(p);
    int v;
    asm volatile("ld.acquire.cta.shared.b32 %0, [%1];" : "=r"(v) : "r"(a));
    return v;
}
__device__ __forceinline__ int ld_vol_sh(const int* p) {
    unsigned a = (unsigned)__cvta_generic_to_shared(p);
    int v;
    asm volatile("ld.volatile.shared.b32 %0, [%1];" : "=r"(v) : "r"(a));
    return v;
}
__device__ __forceinline__ void st_rel_sh(int* p, int v) {
    unsigned a = (unsigned)__cvta_generic_to_shared(p);
    asm volatile("st.release.cta.shared.b32 [%0], %1;" :: "r"(a), "r"(v) : "memory");
}
__device__ __forceinline__ void red_rel_sh(int* p, int v) {
    unsigned a = (unsigned)__cvta_generic_to_shared(p);
    asm volatile("red.release.cta.shared.add.u32 [%0], %1;" :: "r"(a), "r"(v) : "memory");
}

#define LSTM_STEP(XP, TT) do {                                                \
    float a0 = (XP).x, a1 = (XP).y, a2 = (XP).z, a3 = (XP).w;                 \
    float d0 = 0.f, d1 = 0.f, d2 = 0.f, d3 = 0.f;                             \
    _Pragma("unroll")                                                         \
    for (int k = 0; k < 9; k++) {                                             \
        float hk = __shfl_sync(0xFFFFFFFFu, h, k);                            \
        if (k < 5) {                                                          \
            a0 = fmaf(Wi[k], hk, a0); a1 = fmaf(Wf[k], hk, a1);               \
            a2 = fmaf(Wg[k], hk, a2); a3 = fmaf(Wo[k], hk, a3);               \
        } else {                                                              \
            d0 = fmaf(Wi[k], hk, d0); d1 = fmaf(Wf[k], hk, d1);               \
            d2 = fmaf(Wg[k], hk, d2); d3 = fmaf(Wo[k], hk, d3);               \
        }                                                                     \
    }                                                                         \
    float ig = sig_ap(a0 + d0);                                               \
    float fg = sig_ap(a1 + d1);                                               \
    float gg = tanh_ap(a2 + d2);                                              \
    float og = sig_ap(a3 + d3);                                               \
    c = fmaf(fg, c, ig * gg);                                                 \
    h = og * tanh_ap(c);                                                      \
    if (valid) out[(TT) * STRIDE + base_idx] = h;                             \
} while (0)

__global__ __launch_bounds__(416, 1) void lstm_rec_kernel(
    const float* __restrict__ h_in, const float* __restrict__ c_in,
    const float* __restrict__ Whh, float* __restrict__ out)
{
    __shared__ float4 xbuf[2][CH][UPB];   // 41472 B
    __shared__ int ready[2];              // 1 + last chunk loaded into buf
    __shared__ int done[2];               // cumulative consumer releases

    const int tid  = threadIdx.x;
    const int w    = tid >> 5;
    const int lane = tid & 31;
    const int b0blk = blockIdx.x * 9;     // first batch elem of this block
    const int ulim  = (B_SZ - b0blk < 9 ? (B_SZ - b0blk) : 9) * 9; // valid float4s per slab

    if (tid == 0) { ready[0] = 0; ready[1] = 0; done[0] = 0; done[1] = 0; }
    __syncthreads();

    if (w < 9) {
        // ====================== COMPUTE WARP ======================
        const int b0 = b0blk + w;
        const int j  = (lane < 9) ? lane : 8;
        const bool valid = (lane < 9) && (b0 < B_SZ);
        const int b  = (b0 < B_SZ) ? b0 : (B_SZ - 1);

        float Wi[NH], Wf[NH], Wg[NH], Wo[NH];
        #pragma unroll
        for (int k = 0; k < NH; k++) {
            Wi[k] = Whh[(0 * NH + j) * NH + k];
            Wf[k] = Whh[(1 * NH + j) * NH + k];
            Wg[k] = Whh[(2 * NH + j) * NH + k];
            Wo[k] = Whh[(3 * NH + j) * NH + k];
        }
        float h = h_in[b * NH + j];
        float c = c_in[b * NH + j];
        const int base_idx = b * NH + j;
        const int u = w * 9 + j;

        for (int cch = 0; cch < NCH; cch++) {
            const int buf = cch & 1;
            const int t0  = cch * CH;
            if (ld_acq_sh(&ready[buf]) < cch + 1) {
                while (ld_acq_sh(&ready[buf]) < cch + 1) __nanosleep(64);
            }
            const float4* xb = &xbuf[buf][0][u];
            #pragma unroll
            for (int s = 0; s < CH; s++) {
                float4 xp = xb[s * UPB];
                LSTM_STEP(xp, t0 + s);
            }
            __syncwarp();
            if (lane == 0) red_rel_sh(&done[buf], 1);
        }

        if (valid) {
            out[(size_t)T_LEN * STRIDE + base_idx]          = h;  // hn
            out[(size_t)T_LEN * STRIDE + STRIDE + base_idx] = c;  // cn
        }
    } else {
        // ====================== LOADER WARP ======================
        const int lw = w - 9;  // 0..3, each owns 4 timesteps per chunk
        for (int cch = 0; cch < NCH; cch++) {
            const int buf = cch & 1;
            if (cch >= 2) {
                const int need = 9 * (cch >> 1);
                if (ld_vol_sh(&done[buf]) < need) {
                    while (ld_vol_sh(&done[buf]) < need) __nanosleep(128);
                }
            }
            #pragma unroll
            for (int q = 0; q < 4; q++) {
                const int tl = lw * 4 + q;
                const float4* src = g_xpre + (size_t)(cch * CH + tl) * SF4 + b0blk * 9;
                #pragma unroll
                for (int p = 0; p < 3; p++) {
                    const int u = lane + 32 * p;
                    if (u < ulim) xbuf[buf][tl][u] = ldcg4(src + u);
                }
            }
            asm volatile("bar.sync 1, 128;" ::: "memory");
            if (tid == 9 * 32) st_rel_sh(&ready[buf], cch + 1);
        }
    }
}

// ---------------------------------------------------------------------------
extern "C" void kernel_launch(void* const* d_in, const int* in_sizes, int n_in,
                              void* d_out, int out_size) {
    const float* x   = (const float*)d_in[0];
    const float* h   = (const float*)d_in[1];
    const float* c   = (const float*)d_in[2];
    const float* Wih = (const float*)d_in[3];
    const float* Whh = (const float*)d_in[4];
    const float* bih = (const float*)d_in[5];
    const float* bhh = (const float*)d_in[6];
    float* out = (float*)d_out;

    xproj_kernel<<<ROWS / RT, 288>>>(x, Wih, bih, bhh);
    lstm_rec_kernel<<<NCONS, 416>>>(h, c, Whh, out);
}

// round 6
// speedup vs baseline: 2.5718x; 1.3092x over previous
#include <cuda_runtime.h>

#define T_LEN 4096
#define B_SZ  512
#define NIN   42
#define NH    9
#define G4    36             // 4*NH
#define ROWS  (T_LEN * B_SZ) // 2097152
#define KP    44             // padded K (multiple of 4)
#define RT    128            // rows per producer block
#define STRIDE (B_SZ * NH)   // 4608 floats per timestep (output)
#define SF4   4608           // float4s per timestep in g_xpre
#define EPB   4              // batch elements per consumer block
#define NCONS (B_SZ / EPB)   // 128 consumer blocks
#define CH    16             // timesteps per chunk
#define NCH   (T_LEN / CH)   // 256
#define UPB   (EPB * NH)     // 36 float4s per (t, block) slab

// Scratch: gates (i,f,g,o) per (row, j), biases folded in (~302 MB).
__device__ float4 g_xpre[(size_t)ROWS * NH];

// ---------------------------------------------------------------------------
// Kernel 1 (producer): unchanged (measured ~445us standalone).
// ---------------------------------------------------------------------------
__global__ __launch_bounds__(288, 4) void xproj_kernel(
    const float* __restrict__ x, const float* __restrict__ Wih,
    const float* __restrict__ bih, const float* __restrict__ bhh)
{
    __shared__ float xs[RT * KP];
    __shared__ float ws[G4 * KP];
    const int tid  = threadIdx.x;
    const int row0 = blockIdx.x * RT;

    for (int i = tid; i < G4 * NIN; i += 288) {
        int r = i / NIN, k = i - r * NIN;
        int g = r / NH,  j = r - g * NH;
        ws[(j * 4 + g) * KP + k] = Wih[i];
    }
    for (int i = tid; i < G4 * (KP - NIN); i += 288) {
        int r = i / (KP - NIN);
        ws[r * KP + NIN + (i - r * (KP - NIN))] = 0.f;
    }
    const float* xg = x + (size_t)row0 * NIN;
    for (int i = tid; i < RT * NIN; i += 288) {
        int r = i / NIN;
        xs[r * KP + (i - r * NIN)] = xg[i];
    }
    for (int i = tid; i < RT * (KP - NIN); i += 288) {
        int r = i >> 1;
        xs[r * KP + NIN + (i & 1)] = 0.f;
    }
    __syncthreads();

    const int j    = tid >> 5;
    const int lane = tid & 31;

    float acc[4][4];
    #pragma unroll
    for (int r = 0; r < 4; r++)
        #pragma unroll
        for (int g = 0; g < 4; g++) acc[r][g] = 0.f;

    const float4* wv = (const float4*)ws + j * 4 * (KP / 4);
    const float4* xv = (const float4*)xs;

    #pragma unroll
    for (int cch = 0; cch < KP / 4; cch++) {
        float4 w0 = wv[0 * (KP / 4) + cch];
        float4 w1 = wv[1 * (KP / 4) + cch];
        float4 w2 = wv[2 * (KP / 4) + cch];
        float4 w3 = wv[3 * (KP / 4) + cch];
        #pragma unroll
        for (int r = 0; r < 4; r++) {
            float4 xr = xv[(lane + 32 * r) * (KP / 4) + cch];
            acc[r][0] = fmaf(w0.x, xr.x, acc[r][0]);
            acc[r][0] = fmaf(w0.y, xr.y, acc[r][0]);
            acc[r][0] = fmaf(w0.z, xr.z, acc[r][0]);
            acc[r][0] = fmaf(w0.w, xr.w, acc[r][0]);
            acc[r][1] = fmaf(w1.x, xr.x, acc[r][1]);
            acc[r][1] = fmaf(w1.y, xr.y, acc[r][1]);
            acc[r][1] = fmaf(w1.z, xr.z, acc[r][1]);
            acc[r][1] = fmaf(w1.w, xr.w, acc[r][1]);
            acc[r][2] = fmaf(w2.x, xr.x, acc[r][2]);
            acc[r][2] = fmaf(w2.y, xr.y, acc[r][2]);
            acc[r][2] = fmaf(w2.z, xr.z, acc[r][2]);
            acc[r][2] = fmaf(w2.w, xr.w, acc[r][2]);
            acc[r][3] = fmaf(w3.x, xr.x, acc[r][3]);
            acc[r][3] = fmaf(w3.y, xr.y, acc[r][3]);
            acc[r][3] = fmaf(w3.z, xr.z, acc[r][3]);
            acc[r][3] = fmaf(w3.w, xr.w, acc[r][3]);
        }
    }

    float bsum[4];
    #pragma unroll
    for (int g = 0; g < 4; g++) bsum[g] = bih[g * NH + j] + bhh[g * NH + j];

    #pragma unroll
    for (int r = 0; r < 4; r++) {
        int row = row0 + lane + 32 * r;
        float4 o;
        o.x = acc[r][0] + bsum[0];
        o.y = acc[r][1] + bsum[1];
        o.z = acc[r][2] + bsum[2];
        o.w = acc[r][3] + bsum[3];
        g_xpre[(size_t)row * NH + j] = o;
    }
}

// ---------------------------------------------------------------------------
// Consumer: 5 warps/block. Warps 0-3: compute (1 batch elem each → one per
// SMSP). Warp 4: loader streaming x_pre in 16-step chunks, double-buffered.
// ---------------------------------------------------------------------------
__device__ __forceinline__ float tanh_ap(float x) {
    float y;
    asm("tanh.approx.f32 %0, %1;" : "=f"(y) : "f"(x));
    return y;
}
__device__ __forceinline__ float sig_ap(float x) {
    return fmaf(0.5f, tanh_ap(0.5f * x), 0.5f);
}
__device__ __forceinline__ float4 ldcg4(const float4* p) {
    float4 v;
    asm volatile("ld.global.cg.v4.f32 {%0,%1,%2,%3}, [%4];"
                 : "=f"(v.x), "=f"(v.y), "=f"(v.z), "=f"(v.w) : "l"(p));
    return v;
}
__device__ __forceinline__ int ld_acq_sh(const int* p) {
    unsigned a = (unsigned)__cvta_generic_to_shared(p);
    int v;
    asm volatile("ld.acquire.cta.shared.b32 %0, [%1];" : "=r"(v) : "r"(a));
    return v;
}
__device__ __forceinline__ int ld_vol_sh(const int* p) {
    unsigned a = (unsigned)__cvta_generic_to_shared(p);
    int v;
    asm volatile("ld.volatile.shared.b32 %0, [%1];" : "=r"(v) : "r"(a));
    return v;
}
__device__ __forceinline__ void st_rel_sh(int* p, int v) {
    unsigned a = (unsigned)__cvta_generic_to_shared(p);
    asm volatile("st.release.cta.shared.b32 [%0], %1;" :: "r"(a), "r"(v) : "memory");
}
__device__ __forceinline__ void red_rel_sh(int* p, int v) {
    unsigned a = (unsigned)__cvta_generic_to_shared(p);
    asm volatile("red.release.cta.shared.add.u32 [%0], %1;" :: "r"(a), "r"(v) : "memory");
}

#define LSTM_STEP(XP, TT) do {                                                \
    float a0 = (XP).x, a1 = (XP).y, a2 = (XP).z, a3 = (XP).w;                 \
    float d0 = 0.f, d1 = 0.f, d2 = 0.f, d3 = 0.f;                             \
    _Pragma("unroll")                                                         \
    for (int k = 0; k < 9; k++) {                                             \
        float hk = __shfl_sync(0xFFFFFFFFu, h, k);                            \
        if (k < 5) {                                                          \
            a0 = fmaf(Wi[k], hk, a0); a1 = fmaf(Wf[k], hk, a1);               \
            a2 = fmaf(Wg[k], hk, a2); a3 = fmaf(Wo[k], hk, a3);               \
        } else {                                                              \
            d0 = fmaf(Wi[k], hk, d0); d1 = fmaf(Wf[k], hk, d1);               \
            d2 = fmaf(Wg[k], hk, d2); d3 = fmaf(Wo[k], hk, d3);               \
        }                                                                     \
    }                                                                         \
    float ig = sig_ap(a0 + d0);                                               \
    float fg = sig_ap(a1 + d1);                                               \
    float gg = tanh_ap(a2 + d2);                                              \
    float og = sig_ap(a3 + d3);                                               \
    c = fmaf(fg, c, ig * gg);                                                 \
    h = og * tanh_ap(c);                                                      \
    if (valid) out[(TT) * STRIDE + base_idx] = h;                             \
} while (0)

__global__ __launch_bounds__(160, 1) void lstm_rec_kernel(
    const float* __restrict__ h_in, const float* __restrict__ c_in,
    const float* __restrict__ Whh, float* __restrict__ out)
{
    __shared__ float4 xbuf[2][CH][UPB];   // 2*16*36*16 = 18432 B
    __shared__ int ready[2];              // 1 + last chunk loaded into buf
    __shared__ int done[2];               // cumulative compute-warp releases

    const int tid   = threadIdx.x;
    const int w     = tid >> 5;
    const int lane  = tid & 31;
    const int b0blk = blockIdx.x * EPB;   // first batch elem of this block

    if (tid == 0) { ready[0] = 0; ready[1] = 0; done[0] = 0; done[1] = 0; }
    __syncthreads();

    if (w < EPB) {
        // ====================== COMPUTE WARP (1 batch elem) ==================
        const int b = b0blk + w;
        const int j = (lane < 9) ? lane : 8;
        const bool valid = (lane < 9);

        float Wi[NH], Wf[NH], Wg[NH], Wo[NH];
        #pragma unroll
        for (int k = 0; k < NH; k++) {
            Wi[k] = Whh[(0 * NH + j) * NH + k];
            Wf[k] = Whh[(1 * NH + j) * NH + k];
            Wg[k] = Whh[(2 * NH + j) * NH + k];
            Wo[k] = Whh[(3 * NH + j) * NH + k];
        }
        float h = h_in[b * NH + j];
        float c = c_in[b * NH + j];
        const int base_idx = b * NH + j;
        const int u = w * NH + j;

        for (int cch = 0; cch < NCH; cch++) {
            const int buf = cch & 1;
            const int t0  = cch * CH;
            if (ld_acq_sh(&ready[buf]) < cch + 1) {
                while (ld_acq_sh(&ready[buf]) < cch + 1) __nanosleep(64);
            }
            const float4* xb = &xbuf[buf][0][u];
            #pragma unroll
            for (int s = 0; s < CH; s++) {
                float4 xp = xb[s * UPB];
                LSTM_STEP(xp, t0 + s);
            }
            __syncwarp();
            if (lane == 0) red_rel_sh(&done[buf], 1);
        }

        if (valid) {
            out[(size_t)T_LEN * STRIDE + base_idx]          = h;  // hn
            out[(size_t)T_LEN * STRIDE + STRIDE + base_idx] = c;  // cn
        }
    } else {
        // ====================== LOADER WARP (single) ========================
        // Per chunk: CH*UPB = 576 float4 = 18 per lane, fully coalesced
        // (36 float4 per t are contiguous in g_xpre for 4 consecutive b).
        for (int cch = 0; cch < NCH; cch++) {
            const int buf = cch & 1;
            if (cch >= 2) {
                const int need = EPB * (cch >> 1);
                if (ld_vol_sh(&done[buf]) < need) {
                    while (ld_vol_sh(&done[buf]) < need) __nanosleep(128);
                }
            }
            const float4* src = g_xpre + (size_t)(cch * CH) * SF4 + b0blk * NH;
            float4* dst = &xbuf[buf][0][0];
            #pragma unroll
            for (int p = 0; p < 18; p++) {
                const int i  = lane + 32 * p;       // 0..575
                const int tl = i / UPB;
                const int ui = i - tl * UPB;
                dst[i] = ldcg4(src + (size_t)tl * SF4 + ui);
            }
            __syncwarp();
            if (lane == 0) st_rel_sh(&ready[buf], cch + 1);
        }
    }
}

// ---------------------------------------------------------------------------
extern "C" void kernel_launch(void* const* d_in, const int* in_sizes, int n_in,
                              void* d_out, int out_size) {
    const float* x   = (const float*)d_in[0];
    const float* h   = (const float*)d_in[1];
    const float* c   = (const float*)d_in[2];
    const float* Wih = (const float*)d_in[3];
    const float* Whh = (const float*)d_in[4];
    const float* bih = (const float*)d_in[5];
    const float* bhh = (const float*)d_in[6];
    float* out = (float*)d_out;

    xproj_kernel<<<ROWS / RT, 288>>>(x, Wih, bih, bhh);
    lstm_rec_kernel<<<NCONS, 160>>>(h, c, Whh, out);
}

// round 7
// speedup vs baseline: 3.0314x; 1.1787x over previous
#include <cuda_runtime.h>

#define T_LEN 4096
#define B_SZ  512
#define NIN   42
#define NH    9
#define G4    36             // 4*NH
#define ROWS  (T_LEN * B_SZ) // 2097152
#define RT    128            // rows per producer block
#define RTP   128            // row stride in k-major smem
#define STRIDE (B_SZ * NH)   // 4608 floats per timestep (output)
#define SF4   4608           // float4s per timestep in g_xpre
#define EPB   4              // batch elements per consumer block
#define NCONS (B_SZ / EPB)   // 128 consumer blocks
#define CH    16             // timesteps per chunk
#define NCH   (T_LEN / CH)   // 256
#define UPB   (EPB * NH)     // 36 float4s per (t, block) slab

typedef unsigned long long ull;

// Scratch: gates (i,f,g,o) per (row, j), biases folded in (~302 MB).
__device__ float4 g_xpre[(size_t)ROWS * NH];

// ---------------------------------------------------------------------------
// packed f32x2 helpers
// ---------------------------------------------------------------------------
__device__ __forceinline__ ull ffma2(ull a, ull b, ull c) {
    ull d;
    asm("fma.rn.f32x2 %0, %1, %2, %3;" : "=l"(d) : "l"(a), "l"(b), "l"(c));
    return d;
}
__device__ __forceinline__ void lds_v2u64(ull& a, ull& b, const void* p) {
    unsigned addr = (unsigned)__cvta_generic_to_shared(p);
    asm volatile("ld.shared.v2.u64 {%0,%1}, [%2];" : "=l"(a), "=l"(b) : "r"(addr));
}
__device__ __forceinline__ float2 unpack2(ull v) {
    float2 f;
    f.x = __uint_as_float((unsigned)(v & 0xffffffffull));
    f.y = __uint_as_float((unsigned)(v >> 32));
    return f;
}

// ---------------------------------------------------------------------------
// Kernel 1 (producer): FFMA2-based GEMM.
// xs k-major (xs[k*RTP+row]); ws2[k*36 + j*4+g] = (w,w) pre-paired.
// Warp j computes 4 gates of unit j for 4 rows/lane via 8 FFMA2 per k.
// ---------------------------------------------------------------------------
__global__ __launch_bounds__(288, 4) void xproj_kernel(
    const float* __restrict__ x, const float* __restrict__ Wih,
    const float* __restrict__ bih, const float* __restrict__ bhh)
{
    __shared__ float  xs[NIN * RTP];      // 21504 B
    __shared__ float2 ws2[NIN * G4];      // 12096 B
    const int tid  = threadIdx.x;
    const int row0 = blockIdx.x * RT;

    // ---- staging ----
    if (tid < RT) {
        // thread = row; 21 float2 loads (row start 8B-aligned), k-major scatter
        const float2* xr = (const float2*)(x + (size_t)(row0 + tid) * NIN);
        float* dst = xs + tid;
        #pragma unroll
        for (int k2 = 0; k2 < NIN / 2; k2++) {
            float2 v = xr[k2];
            dst[(2 * k2)     * RTP] = v.x;
            dst[(2 * k2 + 1) * RTP] = v.y;
        }
    } else {
        // ws2[k*36 + j*4+g] = (W_ih[(g*9+j)*42 + k],) x2
        for (int i = tid - RT; i < NIN * G4; i += 288 - RT) {
            int k = i / G4, r = i - k * G4;    // r = j*4+g
            int j = r >> 2, g = r & 3;
            float w = Wih[(g * NH + j) * NIN + k];
            ws2[i] = make_float2(w, w);
        }
    }
    __syncthreads();

    const int j    = tid >> 5;   // warp = hidden unit j (0..8)
    const int lane = tid & 31;

    ull acc[2][4];               // [rowpair][gate]
    #pragma unroll
    for (int p = 0; p < 2; p++)
        #pragma unroll
        for (int g = 0; g < 4; g++) acc[p][g] = 0ull;

    const float*  xbase = xs + 4 * lane;        // rows 4l..4l+3 at each k
    const float2* wbase = ws2 + j * 4;

    #pragma unroll
    for (int k = 0; k < NIN; k++) {
        ull xa, xb;                               // (r0,r1), (r2,r3)
        lds_v2u64(xa, xb, xbase + k * RTP);
        ull w0, w1, w2, w3;
        lds_v2u64(w0, w1, wbase + k * G4);        // gates 0,1 (broadcast)
        lds_v2u64(w2, w3, wbase + k * G4 + 2);    // gates 2,3
        acc[0][0] = ffma2(w0, xa, acc[0][0]);
        acc[1][0] = ffma2(w0, xb, acc[1][0]);
        acc[0][1] = ffma2(w1, xa, acc[0][1]);
        acc[1][1] = ffma2(w1, xb, acc[1][1]);
        acc[0][2] = ffma2(w2, xa, acc[0][2]);
        acc[1][2] = ffma2(w2, xb, acc[1][2]);
        acc[0][3] = ffma2(w3, xa, acc[0][3]);
        acc[1][3] = ffma2(w3, xb, acc[1][3]);
    }

    float bsum[4];
    #pragma unroll
    for (int g = 0; g < 4; g++) bsum[g] = bih[g * NH + j] + bhh[g * NH + j];

    #pragma unroll
    for (int p = 0; p < 2; p++) {
        float2 vi = unpack2(acc[p][0]);
        float2 vf = unpack2(acc[p][1]);
        float2 vg = unpack2(acc[p][2]);
        float2 vo = unpack2(acc[p][3]);
        int row = row0 + 4 * lane + 2 * p;
        float4 o0, o1;
        o0.x = vi.x + bsum[0]; o0.y = vf.x + bsum[1];
        o0.z = vg.x + bsum[2]; o0.w = vo.x + bsum[3];
        o1.x = vi.y + bsum[0]; o1.y = vf.y + bsum[1];
        o1.z = vg.y + bsum[2]; o1.w = vo.y + bsum[3];
        g_xpre[(size_t)row * NH + j]       = o0;
        g_xpre[(size_t)(row + 1) * NH + j] = o1;
    }
}

// ---------------------------------------------------------------------------
// Consumer (unchanged from R6): 5 warps/block. Warps 0-3 compute (1 elem each,
// one per SMSP); warp 4 streams x_pre in 16-step chunks, double-buffered.
// ---------------------------------------------------------------------------
__device__ __forceinline__ float tanh_ap(float x) {
    float y;
    asm("tanh.approx.f32 %0, %1;" : "=f"(y) : "f"(x));
    return y;
}
__device__ __forceinline__ float sig_ap(float x) {
    return fmaf(0.5f, tanh_ap(0.5f * x), 0.5f);
}
__device__ __forceinline__ float4 ldcg4(const float4* p) {
    float4 v;
    asm volatile("ld.global.cg.v4.f32 {%0,%1,%2,%3}, [%4];"
                 : "=f"(v.x), "=f"(v.y), "=f"(v.z), "=f"(v.w) : "l"(p));
    return v;
}
__device__ __forceinline__ int ld_acq_sh(const int* p) {
    unsigned a = (unsigned)__cvta_generic_to_shared(p);
    int v;
    asm volatile("ld.acquire.cta.shared.b32 %0, [%1];" : "=r"(v) : "r"(a));
    return v;
}
__device__ __forceinline__ int ld_vol_sh(const int* p) {
    unsigned a = (unsigned)__cvta_generic_to_shared(p);
    int v;
    asm volatile("ld.volatile.shared.b32 %0, [%1];" : "=r"(v) : "r"(a));
    return v;
}
__device__ __forceinline__ void st_rel_sh(int* p, int v) {
    unsigned a = (unsigned)__cvta_generic_to_shared(p);
    asm volatile("st.release.cta.shared.b32 [%0], %1;" :: "r"(a), "r"(v) : "memory");
}
__device__ __forceinline__ void red_rel_sh(int* p, int v) {
    unsigned a = (unsigned)__cvta_generic_to_shared(p);
    asm volatile("red.release.cta.shared.add.u32 [%0], %1;" :: "r"(a), "r"(v) : "memory");
}

#define LSTM_STEP(XP, TT) do {                                                \
    float a0 = (XP).x, a1 = (XP).y, a2 = (XP).z, a3 = (XP).w;                 \
    float d0 = 0.f, d1 = 0.f, d2 = 0.f, d3 = 0.f;                             \
    _Pragma("unroll")                                                         \
    for (int k = 0; k < 9; k++) {                                             \
        float hk = __shfl_sync(0xFFFFFFFFu, h, k);                            \
        if (k < 5) {                                                          \
            a0 = fmaf(Wi[k], hk, a0); a1 = fmaf(Wf[k], hk, a1);               \
            a2 = fmaf(Wg[k], hk, a2); a3 = fmaf(Wo[k], hk, a3);               \
        } else {                                                              \
            d0 = fmaf(Wi[k], hk, d0); d1 = fmaf(Wf[k], hk, d1);               \
            d2 = fmaf(Wg[k], hk, d2); d3 = fmaf(Wo[k], hk, d3);               \
        }                                                                     \
    }                                                                         \
    float ig = sig_ap(a0 + d0);                                               \
    float fg = sig_ap(a1 + d1);                                               \
    float gg = tanh_ap(a2 + d2);                                              \
    float og = sig_ap(a3 + d3);                                               \
    c = fmaf(fg, c, ig * gg);                                                 \
    h = og * tanh_ap(c);                                                      \
    if (valid) out[(TT) * STRIDE + base_idx] = h;                             \
} while (0)

__global__ __launch_bounds__(160, 1) void lstm_rec_kernel(
    const float* __restrict__ h_in, const float* __restrict__ c_in,
    const float* __restrict__ Whh, float* __restrict__ out)
{
    __shared__ float4 xbuf[2][CH][UPB];   // 18432 B
    __shared__ int ready[2];
    __shared__ int done[2];

    const int tid   = threadIdx.x;
    const int w     = tid >> 5;
    const int lane  = tid & 31;
    const int b0blk = blockIdx.x * EPB;

    if (tid == 0) { ready[0] = 0; ready[1] = 0; done[0] = 0; done[1] = 0; }
    __syncthreads();

    if (w < EPB) {
        // ====================== COMPUTE WARP (1 batch elem) ==================
        const int b = b0blk + w;
        const int j = (lane < 9) ? lane : 8;
        const bool valid = (lane < 9);

        float Wi[NH], Wf[NH], Wg[NH], Wo[NH];
        #pragma unroll
        for (int k = 0; k < NH; k++) {
            Wi[k] = Whh[(0 * NH + j) * NH + k];
            Wf[k] = Whh[(1 * NH + j) * NH + k];
            Wg[k] = Whh[(2 * NH + j) * NH + k];
            Wo[k] = Whh[(3 * NH + j) * NH + k];
        }
        float h = h_in[b * NH + j];
        float c = c_in[b * NH + j];
        const int base_idx = b * NH + j;
        const int u = w * NH + j;

        for (int cch = 0; cch < NCH; cch++) {
            const int buf = cch & 1;
            const int t0  = cch * CH;
            if (ld_acq_sh(&ready[buf]) < cch + 1) {
                while (ld_acq_sh(&ready[buf]) < cch + 1) __nanosleep(64);
            }
            const float4* xb = &xbuf[buf][0][u];
            #pragma unroll
            for (int s = 0; s < CH; s++) {
                float4 xp = xb[s * UPB];
                LSTM_STEP(xp, t0 + s);
            }
            __syncwarp();
            if (lane == 0) red_rel_sh(&done[buf], 1);
        }

        if (valid) {
            out[(size_t)T_LEN * STRIDE + base_idx]          = h;  // hn
            out[(size_t)T_LEN * STRIDE + STRIDE + base_idx] = c;  // cn
        }
    } else {
        // ====================== LOADER WARP (single) ========================
        for (int cch = 0; cch < NCH; cch++) {
            const int buf = cch & 1;
            if (cch >= 2) {
                const int need = EPB * (cch >> 1);
                if (ld_vol_sh(&done[buf]) < need) {
                    while (ld_vol_sh(&done[buf]) < need) __nanosleep(128);
                }
            }
            const float4* src = g_xpre + (size_t)(cch * CH) * SF4 + b0blk * NH;
            float4* dst = &xbuf[buf][0][0];
            #pragma unroll
            for (int p = 0; p < 18; p++) {
                const int i  = lane + 32 * p;       // 0..575
                const int tl = i / UPB;
                const int ui = i - tl * UPB;
                dst[i] = ldcg4(src + (size_t)tl * SF4 + ui);
            }
            __syncwarp();
            if (lane == 0) st_rel_sh(&ready[buf], cch + 1);
        }
    }
}

// ---------------------------------------------------------------------------
extern "C" void kernel_launch(void* const* d_in, const int* in_sizes, int n_in,
                              void* d_out, int out_size) {
    const float* x   = (const float*)d_in[0];
    const float* h   = (const float*)d_in[1];
    const float* c   = (const float*)d_in[2];
    const float* Wih = (const float*)d_in[3];
    const float* Whh = (const float*)d_in[4];
    const float* bih = (const float*)d_in[5];
    const float* bhh = (const float*)d_in[6];
    float* out = (float*)d_out;

    xproj_kernel<<<ROWS / RT, 288>>>(x, Wih, bih, bhh);
    lstm_rec_kernel<<<NCONS, 160>>>(h, c, Whh, out);
}

// round 8
// speedup vs baseline: 3.1310x; 1.0328x over previous
#include <cuda_runtime.h>

#define T_LEN 4096
#define B_SZ  512
#define NIN   42
#define NH    9
#define ROWS  (T_LEN * B_SZ) // 2097152
#define PRT   128            // rows per producer block
#define NPROD (ROWS / PRT)   // 16384
#define STRIDE (B_SZ * NH)   // 4608 floats per timestep (output)
#define EPB   4              // batch elements per consumer block
#define NCONS (B_SZ / EPB)   // 128 consumer blocks
#define CH    16             // timesteps per chunk
#define NCH   (T_LEN / CH)   // 256
#define UPB   (EPB * NH)     // 36 float2s per (t, block) slab per half
#define TF4   (B_SZ * NH / 2)// 2304 float4 per timestep per half

typedef unsigned long long ull;

// Split gate storage: h0[row][j] = (i,f), h1[row][j] = (g,o). 151 MB each.
__device__ float4 g_h0[(size_t)ROWS * NH / 2];
__device__ float4 g_h1[(size_t)ROWS * NH / 2];

// ---------------------------------------------------------------------------
// packed f32x2 helpers
// ---------------------------------------------------------------------------
__device__ __forceinline__ ull ffma2(ull a, ull b, ull c) {
    ull d;
    asm("fma.rn.f32x2 %0, %1, %2, %3;" : "=l"(d) : "l"(a), "l"(b), "l"(c));
    return d;
}
__device__ __forceinline__ ull pack2(float a, float b) {
    ull r;
    asm("mov.b64 %0, {%1,%2};" : "=l"(r) : "f"(a), "f"(b));
    return r;
}
__device__ __forceinline__ void lds_v2u64(ull& a, ull& b, const void* p) {
    unsigned addr = (unsigned)__cvta_generic_to_shared(p);
    asm volatile("ld.shared.v2.u64 {%0,%1}, [%2];" : "=l"(a), "=l"(b) : "r"(addr));
}
__device__ __forceinline__ ull lds_u64(const void* p) {
    unsigned addr = (unsigned)__cvta_generic_to_shared(p);
    ull v;
    asm volatile("ld.shared.u64 %0, [%1];" : "=l"(v) : "r"(addr));
    return v;
}
__device__ __forceinline__ float2 unpack2(ull v) {
    float2 f;
    f.x = __uint_as_float((unsigned)(v & 0xffffffffull));
    f.y = __uint_as_float((unsigned)(v >> 32));
    return f;
}

// ---------------------------------------------------------------------------
// Kernel 1 (producer): 64 threads, 128 rows. Warp 0 -> (i,f), warp 1 -> (g,o).
// FFMA2 packed over gate pairs: acc[row][j] = (g_lo, g_hi) directly storable.
// ---------------------------------------------------------------------------
__global__ __launch_bounds__(64, 8) void xproj_kernel(
    const float* __restrict__ x, const float* __restrict__ Wih,
    const float* __restrict__ bih, const float* __restrict__ bhh)
{
    __shared__ float  xs[NIN][PRT];     // 21504 B, k-major
    __shared__ float2 wsH[2][NIN][10];  // 6720 B (j=9 pad for alignment)
    const int tid  = threadIdx.x;
    const int row0 = blockIdx.x * PRT;

    // ---- stage x (thread handles rows tid, tid+64) ----
    #pragma unroll
    for (int rr = 0; rr < 2; rr++) {
        const int r = tid + 64 * rr;
        const float2* xr = (const float2*)(x + (size_t)(row0 + r) * NIN);
        #pragma unroll
        for (int k2 = 0; k2 < NIN / 2; k2++) {
            float2 v = xr[k2];
            xs[2 * k2][r]     = v.x;
            xs[2 * k2 + 1][r] = v.y;
        }
    }
    // ---- stage w pairs: wsH[h][k][j] = (W[2h][j][k], W[2h+1][j][k]) ----
    for (int i = tid; i < NIN * 18; i += 64) {
        int k = i / 18, rem = i - 18 * k;
        int h = rem / 9, j = rem - 9 * h;
        wsH[h][k][j] = make_float2(Wih[((2 * h) * NH + j) * NIN + k],
                                   Wih[((2 * h + 1) * NH + j) * NIN + k]);
    }
    __syncthreads();

    const int w    = tid >> 5;    // gate half: 0=(i,f), 1=(g,o)
    const int lane = tid & 31;    // rows 4*lane .. 4*lane+3

    // accs initialized with folded biases
    ull acc[4][9];
    #pragma unroll
    for (int j = 0; j < 9; j++) {
        float b0 = bih[(2 * w) * NH + j]     + bhh[(2 * w) * NH + j];
        float b1 = bih[(2 * w + 1) * NH + j] + bhh[(2 * w + 1) * NH + j];
        ull bp = pack2(b0, b1);
        #pragma unroll
        for (int r = 0; r < 4; r++) acc[r][j] = bp;
    }

    const float*  xb = &xs[0][4 * lane];
    const float2* wb = &wsH[w][0][0];

    #pragma unroll
    for (int k = 0; k < NIN; k++) {
        ull xa, xbv;
        lds_v2u64(xa, xbv, xb + (size_t)k * PRT);   // rows (0,1),(2,3)
        float2 p0 = unpack2(xa), p1 = unpack2(xbv);
        ull xx0 = pack2(p0.x, p0.x);
        ull xx1 = pack2(p0.y, p0.y);
        ull xx2 = pack2(p1.x, p1.x);
        ull xx3 = pack2(p1.y, p1.y);

        const float2* wk = wb + (size_t)k * 10;
        ull wj[9];
        lds_v2u64(wj[0], wj[1], wk);
        lds_v2u64(wj[2], wj[3], wk + 2);
        lds_v2u64(wj[4], wj[5], wk + 4);
        lds_v2u64(wj[6], wj[7], wk + 6);
        wj[8] = lds_u64(wk + 8);

        #pragma unroll
        for (int j = 0; j < 9; j++) {
            acc[0][j] = ffma2(wj[j], xx0, acc[0][j]);
            acc[1][j] = ffma2(wj[j], xx1, acc[1][j]);
            acc[2][j] = ffma2(wj[j], xx2, acc[2][j]);
            acc[3][j] = ffma2(wj[j], xx3, acc[3][j]);
        }
    }

    // stores: acc[r][j] IS the packed float2 (g_lo, g_hi) for (row, j)
    ull* dst = (ull*)(w == 0 ? g_h0 : g_h1);
    #pragma unroll
    for (int r = 0; r < 4; r++) {
        const size_t row = (size_t)row0 + 4 * lane + r;
        #pragma unroll
        for (int j = 0; j < 9; j++)
            dst[row * NH + j] = acc[r][j];
    }
}

// ---------------------------------------------------------------------------
// Consumer: 5 warps/block. Warps 0-3 compute (1 batch elem each, one per
// SMSP); warp 4 streams both gate-half streams in 16-step chunks (2-deep ring).
// ---------------------------------------------------------------------------
__device__ __forceinline__ float tanh_ap(float x) {
    float y;
    asm("tanh.approx.f32 %0, %1;" : "=f"(y) : "f"(x));
    return y;
}
__device__ __forceinline__ float sig_ap(float x) {
    return fmaf(0.5f, tanh_ap(0.5f * x), 0.5f);
}
__device__ __forceinline__ float4 ldcg4(const float4* p) {
    float4 v;
    asm volatile("ld.global.cg.v4.f32 {%0,%1,%2,%3}, [%4];"
                 : "=f"(v.x), "=f"(v.y), "=f"(v.z), "=f"(v.w) : "l"(p));
    return v;
}
__device__ __forceinline__ int ld_acq_sh(const int* p) {
    unsigned a = (unsigned)__cvta_generic_to_shared(p);
    int v;
    asm volatile("ld.acquire.cta.shared.b32 %0, [%1];" : "=r"(v) : "r"(a));
    return v;
}
__device__ __forceinline__ int ld_vol_sh(const int* p) {
    unsigned a = (unsigned)__cvta_generic_to_shared(p);
    int v;
    asm volatile("ld.volatile.shared.b32 %0, [%1];" : "=r"(v) : "r"(a));
    return v;
}
__device__ __forceinline__ void st_rel_sh(int* p, int v) {
    unsigned a = (unsigned)__cvta_generic_to_shared(p);
    asm volatile("st.release.cta.shared.b32 [%0], %1;" :: "r"(a), "r"(v) : "memory");
}
__device__ __forceinline__ void red_rel_sh(int* p, int v) {
    unsigned a = (unsigned)__cvta_generic_to_shared(p);
    asm volatile("red.release.cta.shared.add.u32 [%0], %1;" :: "r"(a), "r"(v) : "memory");
}

#define LSTM_STEP(XP, TT) do {                                                \
    float a0 = (XP).x, a1 = (XP).y, a2 = (XP).z, a3 = (XP).w;                 \
    float d0 = 0.f, d1 = 0.f, d2 = 0.f, d3 = 0.f;                             \
    _Pragma("unroll")                                                         \
    for (int k = 0; k < 9; k++) {                                             \
        float hk = __shfl_sync(0xFFFFFFFFu, h, k);                            \
        if (k < 5) {                                                          \
            a0 = fmaf(Wi[k], hk, a0); a1 = fmaf(Wf[k], hk, a1);               \
            a2 = fmaf(Wg[k], hk, a2); a3 = fmaf(Wo[k], hk, a3);               \
        } else {                                                              \
            d0 = fmaf(Wi[k], hk, d0); d1 = fmaf(Wf[k], hk, d1);               \
            d2 = fmaf(Wg[k], hk, d2); d3 = fmaf(Wo[k], hk, d3);               \
        }                                                                     \
    }                                                                         \
    float ig = sig_ap(a0 + d0);                                               \
    float fg = sig_ap(a1 + d1);                                               \
    float gg = tanh_ap(a2 + d2);                                              \
    float og = sig_ap(a3 + d3);                                               \
    c = fmaf(fg, c, ig * gg);                                                 \
    h = og * tanh_ap(c);                                                      \
    if (valid) out[(TT) * STRIDE + base_idx] = h;                             \
} while (0)

__global__ __launch_bounds__(160, 1) void lstm_rec_kernel(
    const float* __restrict__ h_in, const float* __restrict__ c_in,
    const float* __restrict__ Whh, float* __restrict__ out)
{
    __shared__ float2 xbufA[2][CH][UPB];  // (i,f) 9216 B
    __shared__ float2 xbufB[2][CH][UPB];  // (g,o) 9216 B
    __shared__ int ready[2];
    __shared__ int done[2];

    const int tid   = threadIdx.x;
    const int w     = tid >> 5;
    const int lane  = tid & 31;
    const int b0blk = blockIdx.x * EPB;

    if (tid == 0) { ready[0] = 0; ready[1] = 0; done[0] = 0; done[1] = 0; }
    __syncthreads();

    if (w < EPB) {
        // ====================== COMPUTE WARP (1 batch elem) ==================
        const int b = b0blk + w;
        const int j = (lane < 9) ? lane : 8;
        const bool valid = (lane < 9);

        float Wi[NH], Wf[NH], Wg[NH], Wo[NH];
        #pragma unroll
        for (int k = 0; k < NH; k++) {
            Wi[k] = Whh[(0 * NH + j) * NH + k];
            Wf[k] = Whh[(1 * NH + j) * NH + k];
            Wg[k] = Whh[(2 * NH + j) * NH + k];
            Wo[k] = Whh[(3 * NH + j) * NH + k];
        }
        float h = h_in[b * NH + j];
        float c = c_in[b * NH + j];
        const int base_idx = b * NH + j;
        const int u = w * NH + j;

        for (int cch = 0; cch < NCH; cch++) {
            const int buf = cch & 1;
            const int t0  = cch * CH;
            if (ld_acq_sh(&ready[buf]) < cch + 1) {
                while (ld_acq_sh(&ready[buf]) < cch + 1) __nanosleep(64);
            }
            #pragma unroll
            for (int s = 0; s < CH; s++) {
                float2 v0 = xbufA[buf][s][u];
                float2 v1 = xbufB[buf][s][u];
                float4 xp = make_float4(v0.x, v0.y, v1.x, v1.y);
                LSTM_STEP(xp, t0 + s);
            }
            __syncwarp();
            if (lane == 0) red_rel_sh(&done[buf], 1);
        }

        if (valid) {
            out[(size_t)T_LEN * STRIDE + base_idx]          = h;  // hn
            out[(size_t)T_LEN * STRIDE + STRIDE + base_idx] = c;  // cn
        }
    } else {
        // ====================== LOADER WARP (single) ========================
        // Per chunk per half: 16 t x 18 float4 contiguous slabs; 2 lanes per t,
        // 9 float4 per lane per half.
        const int tl = lane >> 1;              // 0..15
        const int ui = (lane & 1) * 9;         // 0 or 9
        const size_t boff = (size_t)18 * blockIdx.x;

        for (int cch = 0; cch < NCH; cch++) {
            const int buf = cch & 1;
            if (cch >= 2) {
                const int need = EPB * (cch >> 1);
                if (ld_vol_sh(&done[buf]) < need) {
                    while (ld_vol_sh(&done[buf]) < need) __nanosleep(128);
                }
            }
            const size_t tbase = (size_t)(cch * CH + tl) * TF4 + boff + ui;
            const float4* sA = (const float4*)g_h0 + tbase;
            const float4* sB = (const float4*)g_h1 + tbase;
            float4* dA = (float4*)&xbufA[buf][tl][0] + ui;
            float4* dB = (float4*)&xbufB[buf][tl][0] + ui;
            #pragma unroll
            for (int q = 0; q < 9; q++) dA[q] = ldcg4(sA + q);
            #pragma unroll
            for (int q = 0; q < 9; q++) dB[q] = ldcg4(sB + q);
            __syncwarp();
            if (lane == 0) st_rel_sh(&ready[buf], cch + 1);
        }
    }
}

// ---------------------------------------------------------------------------
extern "C" void kernel_launch(void* const* d_in, const int* in_sizes, int n_in,
                              void* d_out, int out_size) {
    const float* x   = (const float*)d_in[0];
    const float* h   = (const float*)d_in[1];
    const float* c   = (const float*)d_in[2];
    const float* Wih = (const float*)d_in[3];
    const float* Whh = (const float*)d_in[4];
    const float* bih = (const float*)d_in[5];
    const float* bhh = (const float*)d_in[6];
    float* out = (float*)d_out;

    xproj_kernel<<<NPROD, 64>>>(x, Wih, bih, bhh);
    lstm_rec_kernel<<<NCONS, 160>>>(h, c, Whh, out);
}